// round 5
// baseline (speedup 1.0000x reference)
#include <cuda_runtime.h>
#include <cstdint>

// Fixed problem caps (from reference setup_inputs)
static constexpr int NN = 100000;   // nodes
static constexpr int EE = 1600000;  // edges
static constexpr int SCAN_BS = 512;
static constexpr int MAX_NB = (NN + SCAN_BS - 1) / SCAN_BS;  // 196

// Scratch (device globals: allocation-free per harness rules).
// NOTE: only ever referenced from DEVICE code (host-side symbol use is UB).
__device__ float g_dinv[NN];            // deg (then rsqrt(deg))
__device__ int   g_cnt[NN];             // in-degree (excl. self-loop)
__device__ int   g_off[NN];             // CSR offsets (exclusive scan of cnt)
__device__ int   g_cur[NN];             // fill cursors
__device__ int   g_bsum[MAX_NB];        // scan block sums
__device__ int   g_csr_src[EE];         // src node per CSR slot
__device__ float g_csr_nrm[EE];         // norm per CSR slot
__device__ float g_h[NN * 128];         // layer1 GEMM out
__device__ float g_agg[NN * 128];       // layer1 aggregate (pre-bias)
__device__ float g_hz[NN * 64];         // layer2 GEMM out
__device__ float g_agg2[NN * 64];       // layer2 aggregate = z - b2

__global__ void k_init(int n) {
    int i = blockIdx.x * blockDim.x + threadIdx.x;
    if (i < n) { g_dinv[i] = 1.0f; g_cnt[i] = 0; }  // self-loop weight = 1
}

__global__ void k_count(const int* __restrict__ dst, const float* __restrict__ ew, int E) {
    int i = blockIdx.x * blockDim.x + threadIdx.x;
    if (i < E) {
        int d = dst[i];
        atomicAdd(&g_cnt[d], 1);
        atomicAdd(&g_dinv[d], ew[i]);
    }
}

__global__ void k_dinv(int n) {
    int i = blockIdx.x * blockDim.x + threadIdx.x;
    if (i < n) {
        float v = g_dinv[i];
        g_dinv[i] = (v > 0.f) ? rsqrtf(v) : 0.f;
    }
}

// --- exclusive scan of g_cnt -> g_off (2-level) ---
__global__ void k_scan1(int n) {
    __shared__ int sm[SCAN_BS];
    int i = blockIdx.x * SCAN_BS + threadIdx.x;
    int v = (i < n) ? g_cnt[i] : 0;
    sm[threadIdx.x] = v;
    __syncthreads();
    for (int o = 1; o < SCAN_BS; o <<= 1) {
        int t = (threadIdx.x >= o) ? sm[threadIdx.x - o] : 0;
        __syncthreads();
        sm[threadIdx.x] += t;
        __syncthreads();
    }
    if (i < n) g_off[i] = sm[threadIdx.x] - v;  // exclusive within block
    if (threadIdx.x == SCAN_BS - 1) g_bsum[blockIdx.x] = sm[threadIdx.x];
}

__global__ void k_scan2(int nb) {
    __shared__ int sm[256];
    int v = (threadIdx.x < nb) ? g_bsum[threadIdx.x] : 0;
    sm[threadIdx.x] = v;
    __syncthreads();
    for (int o = 1; o < 256; o <<= 1) {
        int t = (threadIdx.x >= o) ? sm[threadIdx.x - o] : 0;
        __syncthreads();
        sm[threadIdx.x] += t;
        __syncthreads();
    }
    if (threadIdx.x < nb) g_bsum[threadIdx.x] = sm[threadIdx.x] - v;  // exclusive
}

__global__ void k_scan3(int n) {
    int i = blockIdx.x * blockDim.x + threadIdx.x;
    if (i < n) {
        int o = g_off[i] + g_bsum[i / SCAN_BS];
        g_off[i] = o;
        g_cur[i] = o;
    }
}

__global__ void k_fill(const int* __restrict__ src, const int* __restrict__ dst,
                       const float* __restrict__ ew, int E) {
    int e = blockIdx.x * blockDim.x + threadIdx.x;
    if (e < E) {
        int s = src[e], d = dst[e];
        int pos = atomicAdd(&g_cur[d], 1);
        g_csr_src[pos] = s;
        g_csr_nrm[pos] = g_dinv[s] * ew[e] * g_dinv[d];
    }
}

// Tiled fp32 GEMM: TM=64 rows/block, full NOUT cols, K=128 in KB=32 chunks.
// LAYER==1: H = x@W1        (A = Xin from harness)
// LAYER==2: A = relu(g_agg + b1); H = A@W2
template <int LAYER>
__global__ void __launch_bounds__(256) k_gemm(const float* __restrict__ Xin,
                                              const float* __restrict__ W,
                                              const float* __restrict__ bin,
                                              int nrows) {
    constexpr int NOUT = (LAYER == 1) ? 128 : 64;
    constexpr int K = 128, KB = 32, TM = 64;
    constexpr int NR = NOUT / 16;  // cols per thread: 8 (L1) / 4 (L2)

    __shared__ float As[KB][TM + 4];  // transposed A tile (k-major)
    __shared__ float Ws[KB][NOUT];

    const float* A = (LAYER == 1) ? Xin : g_agg;   // device-code symbol ref: OK
    float* H = (LAYER == 1) ? g_h : g_hz;

    int tid = threadIdx.x;
    int tx = tid & 15, ty = tid >> 4;
    int row0 = blockIdx.x * TM;

    float acc[4][NR];
#pragma unroll
    for (int i = 0; i < 4; i++)
#pragma unroll
        for (int j = 0; j < NR; j++) acc[i][j] = 0.f;

    for (int k0 = 0; k0 < K; k0 += KB) {
#pragma unroll
        for (int it = 0; it < 2; it++) {
            int fid = tid + it * 256;
            int r = fid >> 3, kq = fid & 7;
            int grow = row0 + r;
            float4 v = make_float4(0.f, 0.f, 0.f, 0.f);
            if (grow < nrows) v = *(const float4*)(A + (size_t)grow * K + k0 + kq * 4);
            if constexpr (LAYER == 2) {
                v.x = fmaxf(v.x + bin[k0 + kq * 4 + 0], 0.f);
                v.y = fmaxf(v.y + bin[k0 + kq * 4 + 1], 0.f);
                v.z = fmaxf(v.z + bin[k0 + kq * 4 + 2], 0.f);
                v.w = fmaxf(v.w + bin[k0 + kq * 4 + 3], 0.f);
            }
            As[kq * 4 + 0][r] = v.x;
            As[kq * 4 + 1][r] = v.y;
            As[kq * 4 + 2][r] = v.z;
            As[kq * 4 + 3][r] = v.w;
        }
        constexpr int WF4 = KB * NOUT / 4;
        const float4* Wg = (const float4*)(W + (size_t)k0 * NOUT);
#pragma unroll
        for (int it = 0; it < WF4 / 256; it++) {
            int f = tid + it * 256;
            int kk = f / (NOUT / 4), j = f % (NOUT / 4);
            *(float4*)&Ws[kk][j * 4] = Wg[f];
        }
        __syncthreads();
#pragma unroll
        for (int kk = 0; kk < KB; kk++) {
            float4 a4 = *(const float4*)&As[kk][ty * 4];
            float av[4] = {a4.x, a4.y, a4.z, a4.w};
            float wv[NR];
#pragma unroll
            for (int j = 0; j < NR; j += 4) {
                float4 w4 = *(const float4*)&Ws[kk][tx * NR + j];
                wv[j] = w4.x; wv[j + 1] = w4.y; wv[j + 2] = w4.z; wv[j + 3] = w4.w;
            }
#pragma unroll
            for (int i = 0; i < 4; i++)
#pragma unroll
                for (int j = 0; j < NR; j++) acc[i][j] = fmaf(av[i], wv[j], acc[i][j]);
        }
        __syncthreads();
    }

#pragma unroll
    for (int i = 0; i < 4; i++) {
        int grow = row0 + ty * 4 + i;
        if (grow >= nrows) continue;
#pragma unroll
        for (int j = 0; j < NR; j += 4) {
            float4 hv = make_float4(acc[i][j], acc[i][j + 1], acc[i][j + 2], acc[i][j + 3]);
            *(float4*)(H + (size_t)grow * NOUT + tx * NR + j) = hv;
        }
    }
}

// Gather-based aggregation: one warp per destination node.
// acc = h[d] * dinv[d]^2 (self-loop) + sum_{incoming e} h[src_e] * norm_e
// LAYER selects (g_h -> g_agg) or (g_hz -> g_agg2) INSIDE device code.
template <int LAYER>
__global__ void __launch_bounds__(256) k_agg(int N) {
    constexpr int NOUT = (LAYER == 1) ? 128 : 64;
    constexpr int V = NOUT / 32;  // floats per lane: 4 (L1) / 2 (L2)
    const float* H = (LAYER == 1) ? g_h : g_hz;
    float* AGG = (LAYER == 1) ? g_agg : g_agg2;

    int d = (int)((blockIdx.x * 256 + threadIdx.x) >> 5);
    int lane = threadIdx.x & 31;
    if (d >= N) return;

    float di = g_dinv[d];
    float d2 = di * di;
    float acc[V];
    {
        const float* p = H + (size_t)d * NOUT + lane * V;
        if constexpr (V == 4) {
            float4 v = *(const float4*)p;
            acc[0] = v.x * d2; acc[1] = v.y * d2; acc[2] = v.z * d2; acc[3] = v.w * d2;
        } else {
            float2 v = *(const float2*)p;
            acc[0] = v.x * d2; acc[1] = v.y * d2;
        }
    }

    int s0 = g_off[d];
    int s1 = s0 + g_cnt[d];
    for (int j0 = s0; j0 < s1; j0 += 32) {
        int m = min(32, s1 - j0);
        int sj = 0; float nj = 0.f;
        if (lane < m) { sj = g_csr_src[j0 + lane]; nj = g_csr_nrm[j0 + lane]; }
        for (int t = 0; t < m; t++) {
            int s = __shfl_sync(0xffffffffu, sj, t);
            float nm = __shfl_sync(0xffffffffu, nj, t);
            const float* p = H + (size_t)s * NOUT + lane * V;
            if constexpr (V == 4) {
                float4 v = *(const float4*)p;
                acc[0] = fmaf(v.x, nm, acc[0]);
                acc[1] = fmaf(v.y, nm, acc[1]);
                acc[2] = fmaf(v.z, nm, acc[2]);
                acc[3] = fmaf(v.w, nm, acc[3]);
            } else {
                float2 v = *(const float2*)p;
                acc[0] = fmaf(v.x, nm, acc[0]);
                acc[1] = fmaf(v.y, nm, acc[1]);
            }
        }
    }

    float* o = AGG + (size_t)d * NOUT + lane * V;
    if constexpr (V == 4) {
        *(float4*)o = make_float4(acc[0], acc[1], acc[2], acc[3]);
    } else {
        *(float2*)o = make_float2(acc[0], acc[1]);
    }
}

// Decode: warp per label edge; z = agg2 + b2 applied on the fly.
__global__ void __launch_bounds__(256) k_decode(const int* __restrict__ eli,
                                                const float* __restrict__ b2,
                                                float* __restrict__ out, int EL) {
    int e = (int)((blockIdx.x * 256 + threadIdx.x) >> 5);
    int lane = threadIdx.x & 31;
    if (e >= EL) return;
    int a = eli[e];
    int b = eli[EL + e];
    float2 za = *(const float2*)(g_agg2 + (size_t)a * 64 + lane * 2);
    float2 zb = *(const float2*)(g_agg2 + (size_t)b * 64 + lane * 2);
    float2 bb = *(const float2*)(b2 + lane * 2);
    float sum = (za.x + bb.x) * (zb.x + bb.x) + (za.y + bb.y) * (zb.y + bb.y);
#pragma unroll
    for (int o = 16; o > 0; o >>= 1) sum += __shfl_xor_sync(0xffffffffu, sum, o);
    if (lane == 0) out[e] = sum;
}

extern "C" void kernel_launch(void* const* d_in, const int* in_sizes, int n_in,
                              void* d_out, int out_size) {
    const float* x = (const float*)d_in[0];
    const int* ei = (const int*)d_in[1];        // int32 (JAX x64 disabled)
    const float* ew = (const float*)d_in[2];
    const int* eli = (const int*)d_in[3];       // int32
    const float* W1 = (const float*)d_in[4];
    const float* b1 = (const float*)d_in[5];
    const float* W2 = (const float*)d_in[6];
    const float* b2 = (const float*)d_in[7];
    float* out = (float*)d_out;

    int N = in_sizes[0] / 128;
    int E = in_sizes[2];
    int EL = in_sizes[3] / 2;
    const int* srcp = ei;
    const int* dstp = ei + E;
    int NB = (N + SCAN_BS - 1) / SCAN_BS;

    // CSR build
    k_init<<<(N + 255) / 256, 256>>>(N);
    k_count<<<(E + 255) / 256, 256>>>(dstp, ew, E);
    k_dinv<<<(N + 255) / 256, 256>>>(N);
    k_scan1<<<NB, SCAN_BS>>>(N);
    k_scan2<<<1, 256>>>(NB);
    k_scan3<<<(N + 255) / 256, 256>>>(N);
    k_fill<<<(E + 255) / 256, 256>>>(srcp, dstp, ew, E);

    // Layer 1
    k_gemm<1><<<(N + 63) / 64, 256>>>(x, W1, nullptr, N);
    k_agg<1><<<(N + 7) / 8, 256>>>(N);

    // Layer 2
    k_gemm<2><<<(N + 63) / 64, 256>>>(nullptr, W2, b1, N);
    k_agg<2><<<(N + 7) / 8, 256>>>(N);

    // Decode
    k_decode<<<(EL + 7) / 8, 256>>>(eli, b2, out, EL);
}